// round 5
// baseline (speedup 1.0000x reference)
#include <cuda_runtime.h>
#include <math.h>

#define BB   2
#define NN   1024
#define DIMM 2048
#define HH   16
#define DHH  128
#define TT   (BB*NN)    // 2048 tokens
#define HD   (HH*DHH)   // 2048
#define MAXP 16
#define NEGV -1e30f

// ---------------- scratch (device globals; zero-init, no allocs) ----------------
__device__ __align__(256) float g_q[TT*HD];
__device__ __align__(256) float g_k[TT*HD];
__device__ __align__(256) float g_v[TT*HD];
__device__ __align__(256) float g_sim [BB*HH*NN*NN];   // scores / attn (ping)
__device__ __align__(256) float g_sim2[BB*HH*NN*NN];   // mixed scores / mixed attn (pong)
__device__ __align__(256) float g_logits[BB*HH*NN*MAXP];
__device__ __align__(256) float g_outh[BB*HH*NN*DHH];
__device__ __align__(256) float g_vg[TT*HD];
__device__ __align__(256) float g_hg[TT*HH];
__device__ __align__(256) float g_gated[TT*HD];

__device__ __forceinline__ float sigmoidf_(float x) { return 1.0f / (1.0f + expf(-x)); }

// ---------------- generic fp32 GEMM: C[M,N] = A[M,K] @ B[K,N] ----------------
// epi: 0 = none, 1 = sigmoid(acc + bias[col])
__global__ void gemm_f32(const float* __restrict__ A, const float* __restrict__ B,
                         float* __restrict__ C, int M, int N, int K,
                         const float* __restrict__ bias, int epi) {
    __shared__ __align__(16) float As[16][64];
    __shared__ __align__(16) float Bs[16][64];
    int tid  = threadIdx.x;                 // 256
    int row0 = blockIdx.y * 64, col0 = blockIdx.x * 64;
    int tx = tid & 15, ty = tid >> 4;
    float acc[4][4];
#pragma unroll
    for (int i = 0; i < 4; i++)
#pragma unroll
        for (int j = 0; j < 4; j++) acc[i][j] = 0.f;

    int ar = tid >> 2, ak = (tid & 3) << 2;   // A: 64 rows x 16 k
    int bk = tid >> 4, bc = (tid & 15) << 2;  // B: 16 k x 64 cols
    const float* Ap = A + (size_t)(row0 + ar) * K + ak;
    const float* Bp = B + (size_t)bk * N + col0 + bc;

    for (int k0 = 0; k0 < K; k0 += 16) {
        float4 a4 = *(const float4*)(Ap + k0);
        As[ak + 0][ar] = a4.x; As[ak + 1][ar] = a4.y;
        As[ak + 2][ar] = a4.z; As[ak + 3][ar] = a4.w;
        float4 b4 = *(const float4*)(Bp + (size_t)k0 * N);
        *(float4*)&Bs[bk][bc] = b4;
        __syncthreads();
#pragma unroll
        for (int kk = 0; kk < 16; kk++) {
            float a[4];
#pragma unroll
            for (int i = 0; i < 4; i++) a[i] = As[kk][ty * 4 + i];
            float4 bq = *(const float4*)&Bs[kk][tx * 4];
            float b[4] = {bq.x, bq.y, bq.z, bq.w};
#pragma unroll
            for (int i = 0; i < 4; i++)
#pragma unroll
                for (int j = 0; j < 4; j++) acc[i][j] = fmaf(a[i], b[j], acc[i][j]);
        }
        __syncthreads();
    }
#pragma unroll
    for (int i = 0; i < 4; i++) {
        int r = row0 + ty * 4 + i;
#pragma unroll
        for (int j = 0; j < 4; j++) {
            int c = col0 + tx * 4 + j;
            float vv = acc[i][j];
            if (epi == 1) vv = sigmoidf_(vv + bias[c]);
            C[(size_t)r * N + c] = vv;
        }
    }
}

// ---------------- L2-norm + rotary (+ CoPE logits for q) ----------------
// grid: (TT*HH, 2) ; y==0 -> q (with logits), y==1 -> k. 128 threads.
__global__ void norm_rotary_kernel(const float* __restrict__ rfreqs,
                                   const float* __restrict__ cope) {
    int vec = blockIdx.x;
    int isK = blockIdx.y;
    int token = vec / HH, h = vec % HH;
    int n = token % NN;
    int d = threadIdx.x;
    float* ptr = (isK ? g_k : g_q) + (size_t)token * HD + h * DHH;

    __shared__ float sv[DHH];
    __shared__ float wred[4];
    __shared__ float s_inv;

    float v = ptr[d];
    float ss = v * v;
#pragma unroll
    for (int o = 16; o > 0; o >>= 1) ss += __shfl_down_sync(0xffffffffu, ss, o);
    if ((d & 31) == 0) wred[d >> 5] = ss;
    __syncthreads();
    if (d == 0) {
        float t = wred[0] + wred[1] + wred[2] + wred[3];
        s_inv = 1.0f / fmaxf(sqrtf(t), 1e-12f);
    }
    __syncthreads();
    float vn = v * s_inv;
    sv[d] = vn;
    __syncthreads();
    float rh = (d & 1) ? sv[d - 1] : -sv[d + 1];
    float f = rfreqs[n * DHH + d];
    float o = vn * cosf(f) + rh * sinf(f);
    ptr[d] = o;
    if (!isK) {
        __syncthreads();
        sv[d] = o;
        __syncthreads();
        if (d < MAXP) {
            float dot = 0.f;
            const float* cp = cope + d * DHH;
#pragma unroll 8
            for (int e = 0; e < DHH; e++) dot = fmaf(sv[e], cp[e], dot);
            int b = token / NN;
            g_logits[(((size_t)(b * HH + h)) * NN + n) * MAXP + d] = dot;
        }
    }
}

// ---------------- sim = 10 * Q @ K^T  (causal tiles only) ----------------
// grid: (16, 16, BB*HH), 256 threads. blockIdx.x = j-tile, y = i-tile.
__global__ void qk_sim_kernel() {
    int jt = blockIdx.x, it = blockIdx.y;
    if (jt > it) return;
    int z = blockIdx.z, b = z / HH, h = z % HH;
    const float* Qb = g_q + (size_t)b * NN * HD + h * DHH;
    const float* Kb = g_k + (size_t)b * NN * HD + h * DHH;
    float* Cb = g_sim + (size_t)z * NN * NN;

    __shared__ __align__(16) float As[32][64];
    __shared__ __align__(16) float Bs[32][64];
    int tid = threadIdx.x;
    int tx = tid & 15, ty = tid >> 4;
    int i0 = it * 64, j0 = jt * 64;
    float acc[4][4];
#pragma unroll
    for (int i = 0; i < 4; i++)
#pragma unroll
        for (int j = 0; j < 4; j++) acc[i][j] = 0.f;

    for (int k0 = 0; k0 < DHH; k0 += 32) {
#pragma unroll
        for (int ii = 0; ii < 2; ii++) {
            int s = tid * 2 + ii;
            int r = s >> 3, k4 = (s & 7) << 2;
            float4 a4 = *(const float4*)&Qb[(size_t)(i0 + r) * HD + k0 + k4];
            As[k4 + 0][r] = a4.x; As[k4 + 1][r] = a4.y;
            As[k4 + 2][r] = a4.z; As[k4 + 3][r] = a4.w;
            float4 b4 = *(const float4*)&Kb[(size_t)(j0 + r) * HD + k0 + k4];
            Bs[k4 + 0][r] = b4.x; Bs[k4 + 1][r] = b4.y;
            Bs[k4 + 2][r] = b4.z; Bs[k4 + 3][r] = b4.w;
        }
        __syncthreads();
#pragma unroll
        for (int kk = 0; kk < 32; kk++) {
            float a[4];
#pragma unroll
            for (int i = 0; i < 4; i++) a[i] = As[kk][ty * 4 + i];
            float4 bq = *(const float4*)&Bs[kk][tx * 4];
            float bv[4] = {bq.x, bq.y, bq.z, bq.w};
#pragma unroll
            for (int i = 0; i < 4; i++)
#pragma unroll
                for (int j = 0; j < 4; j++) acc[i][j] = fmaf(a[i], bv[j], acc[i][j]);
        }
        __syncthreads();
    }
#pragma unroll
    for (int i = 0; i < 4; i++) {
        int r = i0 + ty * 4 + i;
#pragma unroll
        for (int j = 0; j < 4; j++)
            Cb[(size_t)r * NN + j0 + tx * 4 + j] = acc[i][j] * 10.0f;
    }
}

// ---------------- talking-heads mix: out[h] = sum_g th[h,g]*in[g]  (j<=i only) --------
// grid: (4, NN, BB), 256 threads.  in = g_sim, out = g_sim2.
__global__ void mix_heads_kernel(const float* __restrict__ th) {
    int i = blockIdx.y, b = blockIdx.z;
    if ((int)(blockIdx.x * 256) > i) return;
    __shared__ float sth[256];
    sth[threadIdx.x] = th[threadIdx.x];
    __syncthreads();
    int j = blockIdx.x * 256 + threadIdx.x;
    if (j > i) return;
    size_t base = ((size_t)b * HH * NN + i) * NN + j;   // (b, g=0, i, j)
    float vals[16];
#pragma unroll
    for (int g = 0; g < 16; g++) vals[g] = g_sim[base + (size_t)g * NN * NN];
#pragma unroll
    for (int h = 0; h < 16; h++) {
        float s = 0.f;
#pragma unroll
        for (int g = 0; g < 16; g++) s = fmaf(sth[h * 16 + g], vals[g], s);
        g_sim2[base + (size_t)h * NN * NN] = s;
    }
}

// ---------------- CoPE + softmax per row ----------------
// grid: (NN, HH, BB), 256 threads. reads g_sim2, writes attn into g_sim (j<=i).
__global__ void cope_softmax_kernel() {
    int i = blockIdx.x, h = blockIdx.y, b = blockIdx.z;
    int tid = threadIdx.x;
    size_t rowbase = (((size_t)(b * HH + h)) * NN + i) * NN;

    __shared__ float lrow[MAXP];
    __shared__ float wsum[8], woff[8];
    __shared__ float s_total, s_m, s_sum;

    if (tid < MAXP)
        lrow[tid] = g_logits[(((size_t)(b * HH + h)) * NN + i) * MAXP + tid];

    int j0 = tid * 4;
    float v[4], g[4];
#pragma unroll
    for (int c = 0; c < 4; c++) {
        int j = j0 + c;
        if (j <= i) { v[c] = g_sim2[rowbase + j]; g[c] = sigmoidf_(v[c]); }
        else        { v[c] = NEGV;               g[c] = 0.f; }
    }
    float lp[4];
    lp[0] = 0.f; lp[1] = g[0]; lp[2] = lp[1] + g[1]; lp[3] = lp[2] + g[2];
    float tsum = lp[3] + g[3];

    unsigned lane = tid & 31, wid = tid >> 5;
    float incl = tsum;
#pragma unroll
    for (int o = 1; o < 32; o <<= 1) {
        float t = __shfl_up_sync(0xffffffffu, incl, o);
        if (lane >= o) incl += t;
    }
    if (lane == 31) wsum[wid] = incl;
    __syncthreads();
    if (tid == 0) {
        float run = 0.f;
        for (int w = 0; w < 8; w++) { woff[w] = run; run += wsum[w]; }
        s_total = run;
    }
    __syncthreads();
    float basex = (incl - tsum) + woff[wid];
    float total = s_total;

    float nv[4];
#pragma unroll
    for (int c = 0; c < 4; c++) {
        int j = j0 + c;
        if (j <= i) {
            float pos = total - (basex + lp[c]);
            pos = fminf(fmaxf(pos, 0.f), 15.0f);
            float pf = floorf(pos);
            float w  = pos - pf;
            int fi = (int)pf;
            int ci = (int)ceilf(pos);
            nv[c] = v[c] + lrow[ci] * w + lrow[fi] * (1.0f - w);
        } else nv[c] = NEGV;
    }
    // max
    float m = fmaxf(fmaxf(nv[0], nv[1]), fmaxf(nv[2], nv[3]));
#pragma unroll
    for (int o = 16; o > 0; o >>= 1) m = fmaxf(m, __shfl_xor_sync(0xffffffffu, m, o));
    if (lane == 0) wsum[wid] = m;
    __syncthreads();
    if (tid == 0) {
        float mm = wsum[0];
        for (int w = 1; w < 8; w++) mm = fmaxf(mm, wsum[w]);
        s_m = mm;
    }
    __syncthreads();
    m = s_m;
    float e[4]; float ls = 0.f;
#pragma unroll
    for (int c = 0; c < 4; c++) { e[c] = expf(nv[c] - m); ls += e[c]; }
#pragma unroll
    for (int o = 16; o > 0; o >>= 1) ls += __shfl_xor_sync(0xffffffffu, ls, o);
    if (lane == 0) woff[wid] = ls;
    __syncthreads();
    if (tid == 0) {
        float t = 0.f;
        for (int w = 0; w < 8; w++) t += woff[w];
        s_sum = t;
    }
    __syncthreads();
    float inv = 1.0f / s_sum;
#pragma unroll
    for (int c = 0; c < 4; c++) {
        int j = j0 + c;
        if (j <= i) g_sim[rowbase + j] = e[c] * inv;
    }
}

// ---------------- out = attn2 @ V per (b,h); triangular K-loop ----------------
// grid: (16, BB*HH), 256 threads. reads g_sim2 (mixed attn), writes g_outh.
__global__ void av_kernel() {
    int i0 = blockIdx.x * 64;
    int z = blockIdx.y, b = z / HH, h = z % HH;
    const float* At = g_sim2 + (size_t)z * NN * NN;
    const float* Vb = g_v + (size_t)b * NN * HD + h * DHH;

    __shared__ __align__(16) float As[32][64];
    __shared__ __align__(16) float Bs[32][128];
    int tid = threadIdx.x;
    int tx = tid & 31, ty = tid >> 5;
    float acc[8][4];
#pragma unroll
    for (int i = 0; i < 8; i++)
#pragma unroll
        for (int j = 0; j < 4; j++) acc[i][j] = 0.f;

    int jmax = i0 + 64;
    for (int j0 = 0; j0 < jmax; j0 += 32) {
#pragma unroll
        for (int ii = 0; ii < 2; ii++) {
            int s = tid * 2 + ii;
            int r = s >> 3, j4 = (s & 7) << 2;
            int row = i0 + r;
            float4 a4 = *(const float4*)&At[(size_t)row * NN + j0 + j4];
            As[j4 + 0][r] = (j0 + j4 + 0 <= row) ? a4.x : 0.f;
            As[j4 + 1][r] = (j0 + j4 + 1 <= row) ? a4.y : 0.f;
            As[j4 + 2][r] = (j0 + j4 + 2 <= row) ? a4.z : 0.f;
            As[j4 + 3][r] = (j0 + j4 + 3 <= row) ? a4.w : 0.f;
        }
#pragma unroll
        for (int ii = 0; ii < 4; ii++) {
            int s = tid * 4 + ii;
            int jj = s >> 5, d4 = (s & 31) << 2;
            *(float4*)&Bs[jj][d4] = *(const float4*)&Vb[(size_t)(j0 + jj) * HD + d4];
        }
        __syncthreads();
#pragma unroll
        for (int jj = 0; jj < 32; jj++) {
            float a[8];
#pragma unroll
            for (int i = 0; i < 8; i++) a[i] = As[jj][ty * 8 + i];
            float4 bq = *(const float4*)&Bs[jj][tx * 4];
            float bv[4] = {bq.x, bq.y, bq.z, bq.w};
#pragma unroll
            for (int i = 0; i < 8; i++)
#pragma unroll
                for (int j = 0; j < 4; j++) acc[i][j] = fmaf(a[i], bv[j], acc[i][j]);
        }
        __syncthreads();
    }
#pragma unroll
    for (int i = 0; i < 8; i++) {
        size_t obase = ((size_t)z * NN + i0 + ty * 8 + i) * DHH + tx * 4;
#pragma unroll
        for (int j = 0; j < 4; j++) g_outh[obase + j] = acc[i][j];
    }
}

// ---------------- head gate: sigmoid(x @ w_hgate + b) ----------------
// grid: TT, 512 threads (16 warps, one per head)
__global__ void hgate_kernel(const float* __restrict__ x, const float* __restrict__ wh,
                             const float* __restrict__ bh) {
    int token = blockIdx.x;
    __shared__ __align__(16) float sx[DIMM];
    int tid = threadIdx.x;
    *(float4*)&sx[tid * 4] = *(const float4*)&x[(size_t)token * DIMM + tid * 4];
    __syncthreads();
    int h = tid >> 5, lane = tid & 31;
    float s = 0.f;
    for (int e = lane; e < DIMM; e += 32) s = fmaf(sx[e], wh[e * HH + h], s);
#pragma unroll
    for (int o = 16; o > 0; o >>= 1) s += __shfl_xor_sync(0xffffffffu, s, o);
    if (lane == 0) g_hg[token * HH + h] = sigmoidf_(s + bh[h]);
}

// ---------------- apply gates, merge heads ----------------
__global__ void gate_mul_kernel() {
    int idx = blockIdx.x * 256 + threadIdx.x;   // TT*HD total
    int token = idx >> 11;
    int c = idx & 2047;
    int h = c >> 7, d = c & 127;
    int b = token >> 10, n = token & 1023;
    float o = g_outh[(((size_t)(b * HH + h)) * NN + n) * DHH + d];
    g_gated[idx] = o * g_hg[token * HH + h] * g_vg[idx];
}

// ---------------- launch ----------------
extern "C" void kernel_launch(void* const* d_in, const int* in_sizes, int n_in,
                              void* d_out, int out_size) {
    const float* x    = (const float*)d_in[0];
    const float* rf   = (const float*)d_in[1];
    const float* wq   = (const float*)d_in[2];
    const float* wk   = (const float*)d_in[3];
    const float* wv   = (const float*)d_in[4];
    const float* cope = (const float*)d_in[5];
    const float* thp  = (const float*)d_in[6];
    const float* tho  = (const float*)d_in[7];
    const float* wvg  = (const float*)d_in[8];
    const float* bvg  = (const float*)d_in[9];
    const float* whg  = (const float*)d_in[10];
    const float* bhg  = (const float*)d_in[11];
    const float* wout = (const float*)d_in[12];
    float* out = (float*)d_out;

    void *pq, *pk, *pv, *pvg, *pgated;
    cudaGetSymbolAddress(&pq, g_q);
    cudaGetSymbolAddress(&pk, g_k);
    cudaGetSymbolAddress(&pv, g_v);
    cudaGetSymbolAddress(&pvg, g_vg);
    cudaGetSymbolAddress(&pgated, g_gated);

    dim3 gBig(HD / 64, TT / 64);   // 32 x 32

    gemm_f32<<<gBig, 256>>>(x, wq, (float*)pq, TT, HD, DIMM, nullptr, 0);
    gemm_f32<<<gBig, 256>>>(x, wk, (float*)pk, TT, HD, DIMM, nullptr, 0);
    gemm_f32<<<gBig, 256>>>(x, wv, (float*)pv, TT, HD, DIMM, nullptr, 0);

    norm_rotary_kernel<<<dim3(TT * HH, 2), 128>>>(rf, cope);

    qk_sim_kernel<<<dim3(16, 16, BB * HH), 256>>>();

    mix_heads_kernel<<<dim3(4, NN, BB), 256>>>(thp);          // g_sim -> g_sim2

    cope_softmax_kernel<<<dim3(NN, HH, BB), 256>>>();         // g_sim2 -> attn in g_sim

    mix_heads_kernel<<<dim3(4, NN, BB), 256>>>(tho);          // g_sim -> g_sim2

    av_kernel<<<dim3(16, BB * HH), 256>>>();                  // g_sim2 @ V -> g_outh

    hgate_kernel<<<TT, 512>>>(x, whg, bhg);
    gemm_f32<<<gBig, 256>>>(x, wvg, (float*)pvg, TT, HD, DIMM, bvg, 1);
    gate_mul_kernel<<<(TT * HD) / 256, 256>>>();

    gemm_f32<<<gBig, 256>>>((float*)pgated, wout, out, TT, DIMM, HD, nullptr, 0);
}

// round 6
// speedup vs baseline: 2.0004x; 2.0004x over previous
#include <cuda_runtime.h>
#include <math.h>

#define BB   2
#define NN   1024
#define DIMM 2048
#define HH   16
#define DHH  128
#define TT   (BB*NN)    // 2048 tokens
#define HD   (HH*DHH)   // 2048
#define MAXP 16
#define NEGV -1e30f

// ---------------- scratch (device globals; zero-init, no allocs) ----------------
__device__ __align__(256) float g_q[TT*HD];
__device__ __align__(256) float g_k[TT*HD];
__device__ __align__(256) float g_v[TT*HD];
__device__ __align__(256) float g_sim [BB*HH*NN*NN];   // scores / attn (ping)
__device__ __align__(256) float g_sim2[BB*HH*NN*NN];   // mixed scores / mixed attn (pong)
__device__ __align__(256) float g_logits[BB*HH*NN*MAXP];
__device__ __align__(256) float g_outh[BB*HH*NN*DHH];
__device__ __align__(256) float g_vg[TT*HD];
__device__ __align__(256) float g_hg[TT*HH];
__device__ __align__(256) float g_gated[TT*HD];
__device__ __align__(256) float g_cos[NN*DHH];
__device__ __align__(256) float g_sin[NN*DHH];

__device__ __forceinline__ float sigmoidf_(float x) { return 1.0f / (1.0f + expf(-x)); }

__device__ __forceinline__ unsigned f2tf(float x) {
    unsigned u; asm("cvt.rna.tf32.f32 %0, %1;" : "=r"(u) : "f"(x)); return u;
}

#define MMA_TF32(cc, aa, bb)                                                     \
    asm volatile("mma.sync.aligned.m16n8k8.row.col.f32.tf32.tf32.f32 "           \
                 "{%0,%1,%2,%3},{%4,%5,%6,%7},{%8,%9},{%0,%1,%2,%3};"            \
                 : "+f"((cc)[0]), "+f"((cc)[1]), "+f"((cc)[2]), "+f"((cc)[3])    \
                 : "r"((aa)[0]), "r"((aa)[1]), "r"((aa)[2]), "r"((aa)[3]),       \
                   "r"((bb)[0]), "r"((bb)[1]))

// =====================================================================
// Unified tf32 tensor-core GEMM.
//   C[M,N] = scale * A[M,K] @ B[K,N]   (+ optional sigmoid(·+bias) epilogue)
// flags: 1 = transB (B[k][n] = Bsrc[n*ldb + k])
//        2 = causal block skip (skip tiles with jt > it)
//        4 = causal A mask (A[i][k]=0 for k>i) + triangular K bound
//        8 = sigmoid(acc + bias[col]) epilogue
// Per-z offsets: z -> (bz = z>>4, hz = z&15); off = bz*s?b + hz*s?h
// Block: 256 threads; tile 128x128x32; warp tile 64x32 (2x4 warps).
// =====================================================================
__global__ __launch_bounds__(256) void gemm_tf32(
    const float* __restrict__ A, int lda, long long sAb, long long sAh,
    const float* __restrict__ B, int ldb, long long sBb, long long sBh,
    float* __restrict__ C, int ldc, long long sCb, long long sCh,
    int M, int N, int K, int flags, const float* __restrict__ bias, float scale)
{
    if ((flags & 2) && blockIdx.x > blockIdx.y) return;
    int z = blockIdx.z, bz = z >> 4, hz = z & 15;
    const float* Ab = A + bz * sAb + hz * sAh;
    const float* Bb = B + bz * sBb + hz * sBh;
    float*       Cb = C + bz * sCb + hz * sCh;

    __shared__ __align__(16) unsigned As[32][129];
    __shared__ __align__(16) unsigned Bs[32][132];

    int tid = threadIdx.x, lane = tid & 31, wid = tid >> 5;
    int wm = wid >> 2, wn = wid & 3;
    int g = lane >> 2, tg = lane & 3;
    int row0 = blockIdx.y * 128, col0 = blockIdx.x * 128;

    float c[4][4][4];
#pragma unroll
    for (int mt = 0; mt < 4; mt++)
#pragma unroll
        for (int nt = 0; nt < 4; nt++)
#pragma unroll
            for (int e = 0; e < 4; e++) c[mt][nt][e] = 0.f;

    int kmax = K;
    if (flags & 4) { int t = row0 + 128; if (t < kmax) kmax = t; }

    int la_r = tid >> 3;          // 0..31
    int la_k = (tid & 7) * 4;     // 0..28
    int lb_k = tid >> 5;          // 0..7
    int lb_n = lane * 4;          // 0..124

    for (int k0 = 0; k0 < kmax; k0 += 32) {
        // ---- A tile: 128 rows x 32 k, stored As[k][m] ----
#pragma unroll
        for (int p = 0; p < 4; p++) {
            int r = p * 32 + la_r;
            float4 v = *(const float4*)(Ab + (size_t)(row0 + r) * lda + k0 + la_k);
            if (flags & 4) {
                int gi = row0 + r, gj = k0 + la_k;
                if (gj + 0 > gi) v.x = 0.f;
                if (gj + 1 > gi) v.y = 0.f;
                if (gj + 2 > gi) v.z = 0.f;
                if (gj + 3 > gi) v.w = 0.f;
            }
            As[la_k + 0][r] = f2tf(v.x);
            As[la_k + 1][r] = f2tf(v.y);
            As[la_k + 2][r] = f2tf(v.z);
            As[la_k + 3][r] = f2tf(v.w);
        }
        // ---- B tile: stored Bs[k][n] ----
        if (flags & 1) {
#pragma unroll
            for (int p = 0; p < 4; p++) {
                int n = p * 32 + la_r;
                float4 v = *(const float4*)(Bb + (size_t)(col0 + n) * ldb + k0 + la_k);
                Bs[la_k + 0][n] = f2tf(v.x);
                Bs[la_k + 1][n] = f2tf(v.y);
                Bs[la_k + 2][n] = f2tf(v.z);
                Bs[la_k + 3][n] = f2tf(v.w);
            }
        } else {
#pragma unroll
            for (int p = 0; p < 4; p++) {
                int kk = p * 8 + lb_k;
                float4 v = *(const float4*)(Bb + (size_t)(k0 + kk) * ldb + col0 + lb_n);
                uint4 u;
                u.x = f2tf(v.x); u.y = f2tf(v.y); u.z = f2tf(v.z); u.w = f2tf(v.w);
                *(uint4*)&Bs[kk][lb_n] = u;
            }
        }
        __syncthreads();
#pragma unroll
        for (int ks = 0; ks < 4; ks++) {
            int kb = ks * 8;
            unsigned a[4][4], b[4][2];
#pragma unroll
            for (int mt = 0; mt < 4; mt++) {
                int m = wm * 64 + mt * 16 + g;
                a[mt][0] = As[kb + tg][m];
                a[mt][1] = As[kb + tg][m + 8];
                a[mt][2] = As[kb + tg + 4][m];
                a[mt][3] = As[kb + tg + 4][m + 8];
            }
#pragma unroll
            for (int nt = 0; nt < 4; nt++) {
                int n = wn * 32 + nt * 8 + g;
                b[nt][0] = Bs[kb + tg][n];
                b[nt][1] = Bs[kb + tg + 4][n];
            }
#pragma unroll
            for (int mt = 0; mt < 4; mt++)
#pragma unroll
                for (int nt = 0; nt < 4; nt++)
                    MMA_TF32(c[mt][nt], a[mt], b[nt]);
        }
        __syncthreads();
    }

    // ---- epilogue ----
#pragma unroll
    for (int mt = 0; mt < 4; mt++) {
        int r0 = row0 + wm * 64 + mt * 16 + g;
#pragma unroll
        for (int nt = 0; nt < 4; nt++) {
            int col = col0 + wn * 32 + nt * 8 + 2 * tg;
            float v0 = c[mt][nt][0] * scale, v1 = c[mt][nt][1] * scale;
            float v2 = c[mt][nt][2] * scale, v3 = c[mt][nt][3] * scale;
            if (flags & 8) {
                v0 = sigmoidf_(v0 + bias[col]);     v1 = sigmoidf_(v1 + bias[col + 1]);
                v2 = sigmoidf_(v2 + bias[col]);     v3 = sigmoidf_(v3 + bias[col + 1]);
            }
            float2 p0; p0.x = v0; p0.y = v1;
            float2 p1; p1.x = v2; p1.y = v3;
            *(float2*)(Cb + (size_t)r0 * ldc + col)       = p0;
            *(float2*)(Cb + (size_t)(r0 + 8) * ldc + col) = p1;
        }
    }
}

// ---------------- rope table: cos/sin of rotary_freqs ----------------
__global__ void rope_cs_kernel(const float* __restrict__ rf) {
    int idx = blockIdx.x * 256 + threadIdx.x;
    float f = rf[idx];
    g_cos[idx] = cosf(f);
    g_sin[idx] = sinf(f);
}

// ---------------- warp-per-vector L2-norm + rotary (+ CoPE logits for q) ----------
// grid: 8192 blocks x 256 threads; warp w handles one (token,head) for q or k.
__global__ void norm_rot2_kernel(const float* __restrict__ cope) {
    int lane = threadIdx.x & 31;
    int w = blockIdx.x * 8 + (threadIdx.x >> 5);
    const int NV = TT * HH;
    int isK = (w >= NV) ? 1 : 0;
    int vec = isK ? (w - NV) : w;
    int token = vec >> 4, h = vec & 15;
    int n = token & (NN - 1), b = token >> 10;

    float* ptr = (isK ? g_k : g_q) + (size_t)token * HD + h * DHH + lane * 4;
    float4 v = *(float4*)ptr;
    float ss = v.x * v.x + v.y * v.y + v.z * v.z + v.w * v.w;
#pragma unroll
    for (int o = 16; o > 0; o >>= 1) ss += __shfl_xor_sync(0xffffffffu, ss, o);
    float inv = 1.0f / fmaxf(sqrtf(ss), 1e-12f);
    v.x *= inv; v.y *= inv; v.z *= inv; v.w *= inv;

    float4 cs = *(const float4*)(g_cos + n * DHH + lane * 4);
    float4 sn = *(const float4*)(g_sin + n * DHH + lane * 4);
    float4 o;
    o.x = v.x * cs.x - v.y * sn.x;
    o.y = v.y * cs.y + v.x * sn.y;
    o.z = v.z * cs.z - v.w * sn.z;
    o.w = v.w * cs.w + v.z * sn.w;
    *(float4*)ptr = o;

    if (!isK) {
        float myv = 0.f;
#pragma unroll
        for (int p = 0; p < MAXP; p++) {
            float4 cp = *(const float4*)(cope + p * DHH + lane * 4);
            float pa = o.x * cp.x + o.y * cp.y + o.z * cp.z + o.w * cp.w;
#pragma unroll
            for (int off = 16; off > 0; off >>= 1)
                pa += __shfl_xor_sync(0xffffffffu, pa, off);
            if (lane == p) myv = pa;
        }
        if (lane < MAXP)
            g_logits[((size_t)(b * HH + h) * NN + n) * MAXP + lane] = myv;
    }
}

// ---------------- talking-heads mix (j<=i only) ----------------
__global__ void mix_heads_kernel(const float* __restrict__ th) {
    int i = blockIdx.y, b = blockIdx.z;
    if ((int)(blockIdx.x * 256) > i) return;
    __shared__ float sth[256];
    sth[threadIdx.x] = th[threadIdx.x];
    __syncthreads();
    int j = blockIdx.x * 256 + threadIdx.x;
    if (j > i) return;
    size_t base = ((size_t)b * HH * NN + i) * NN + j;
    float vals[16];
#pragma unroll
    for (int g = 0; g < 16; g++) vals[g] = g_sim[base + (size_t)g * NN * NN];
#pragma unroll
    for (int h = 0; h < 16; h++) {
        float s = 0.f;
#pragma unroll
        for (int g = 0; g < 16; g++) s = fmaf(sth[h * 16 + g], vals[g], s);
        g_sim2[base + (size_t)h * NN * NN] = s;
    }
}

// ---------------- CoPE + softmax per row ----------------
__global__ void cope_softmax_kernel() {
    int i = blockIdx.x, h = blockIdx.y, b = blockIdx.z;
    int tid = threadIdx.x;
    size_t rowbase = (((size_t)(b * HH + h)) * NN + i) * NN;

    __shared__ float lrow[MAXP];
    __shared__ float wsum[8], woff[8];
    __shared__ float s_total, s_m, s_sum;

    if (tid < MAXP)
        lrow[tid] = g_logits[(((size_t)(b * HH + h)) * NN + i) * MAXP + tid];

    int j0 = tid * 4;
    float v[4], g[4];
#pragma unroll
    for (int c = 0; c < 4; c++) {
        int j = j0 + c;
        if (j <= i) { v[c] = g_sim2[rowbase + j]; g[c] = sigmoidf_(v[c]); }
        else        { v[c] = NEGV;               g[c] = 0.f; }
    }
    float lp[4];
    lp[0] = 0.f; lp[1] = g[0]; lp[2] = lp[1] + g[1]; lp[3] = lp[2] + g[2];
    float tsum = lp[3] + g[3];

    unsigned lane = tid & 31, wid = tid >> 5;
    float incl = tsum;
#pragma unroll
    for (int o = 1; o < 32; o <<= 1) {
        float t = __shfl_up_sync(0xffffffffu, incl, o);
        if (lane >= o) incl += t;
    }
    if (lane == 31) wsum[wid] = incl;
    __syncthreads();
    if (tid == 0) {
        float run = 0.f;
        for (int w = 0; w < 8; w++) { woff[w] = run; run += wsum[w]; }
        s_total = run;
    }
    __syncthreads();
    float basex = (incl - tsum) + woff[wid];
    float total = s_total;

    float nv[4];
#pragma unroll
    for (int c = 0; c < 4; c++) {
        int j = j0 + c;
        if (j <= i) {
            float pos = total - (basex + lp[c]);
            pos = fminf(fmaxf(pos, 0.f), 15.0f);
            float pf = floorf(pos);
            float w  = pos - pf;
            int fi = (int)pf;
            int ci = (int)ceilf(pos);
            nv[c] = v[c] + lrow[ci] * w + lrow[fi] * (1.0f - w);
        } else nv[c] = NEGV;
    }
    float m = fmaxf(fmaxf(nv[0], nv[1]), fmaxf(nv[2], nv[3]));
#pragma unroll
    for (int o = 16; o > 0; o >>= 1) m = fmaxf(m, __shfl_xor_sync(0xffffffffu, m, o));
    if (lane == 0) wsum[wid] = m;
    __syncthreads();
    if (tid == 0) {
        float mm = wsum[0];
        for (int w = 1; w < 8; w++) mm = fmaxf(mm, wsum[w]);
        s_m = mm;
    }
    __syncthreads();
    m = s_m;
    float e[4]; float ls = 0.f;
#pragma unroll
    for (int c = 0; c < 4; c++) { e[c] = expf(nv[c] - m); ls += e[c]; }
#pragma unroll
    for (int o = 16; o > 0; o >>= 1) ls += __shfl_xor_sync(0xffffffffu, ls, o);
    if (lane == 0) woff[wid] = ls;
    __syncthreads();
    if (tid == 0) {
        float t = 0.f;
        for (int w = 0; w < 8; w++) t += woff[w];
        s_sum = t;
    }
    __syncthreads();
    float invs = 1.0f / s_sum;
#pragma unroll
    for (int c = 0; c < 4; c++) {
        int j = j0 + c;
        if (j <= i) g_sim[rowbase + j] = e[c] * invs;
    }
}

// ---------------- head gate ----------------
__global__ void hgate_kernel(const float* __restrict__ x, const float* __restrict__ wh,
                             const float* __restrict__ bh) {
    int token = blockIdx.x;
    __shared__ __align__(16) float sx[DIMM];
    int tid = threadIdx.x;
    *(float4*)&sx[tid * 4] = *(const float4*)&x[(size_t)token * DIMM + tid * 4];
    __syncthreads();
    int h = tid >> 5, lane = tid & 31;
    float s = 0.f;
    for (int e = lane; e < DIMM; e += 32) s = fmaf(sx[e], wh[e * HH + h], s);
#pragma unroll
    for (int o = 16; o > 0; o >>= 1) s += __shfl_xor_sync(0xffffffffu, s, o);
    if (lane == 0) g_hg[token * HH + h] = sigmoidf_(s + bh[h]);
}

// ---------------- apply gates, merge heads ----------------
__global__ void gate_mul_kernel() {
    int idx = blockIdx.x * 256 + threadIdx.x;
    int token = idx >> 11;
    int c = idx & 2047;
    int h = c >> 7, d = c & 127;
    int b = token >> 10, n = token & 1023;
    float o = g_outh[(((size_t)(b * HH + h)) * NN + n) * DHH + d];
    g_gated[idx] = o * g_hg[token * HH + h] * g_vg[idx];
}

// ---------------- launch ----------------
extern "C" void kernel_launch(void* const* d_in, const int* in_sizes, int n_in,
                              void* d_out, int out_size) {
    const float* x    = (const float*)d_in[0];
    const float* rf   = (const float*)d_in[1];
    const float* wq   = (const float*)d_in[2];
    const float* wk   = (const float*)d_in[3];
    const float* wv   = (const float*)d_in[4];
    const float* cope = (const float*)d_in[5];
    const float* thp  = (const float*)d_in[6];
    const float* tho  = (const float*)d_in[7];
    const float* wvg  = (const float*)d_in[8];
    const float* bvg  = (const float*)d_in[9];
    const float* whg  = (const float*)d_in[10];
    const float* bhg  = (const float*)d_in[11];
    const float* wout = (const float*)d_in[12];
    float* out = (float*)d_out;

    void *pq, *pk, *pv, *psim, *psim2, *pouth, *pvg, *pgated;
    cudaGetSymbolAddress(&pq, g_q);
    cudaGetSymbolAddress(&pk, g_k);
    cudaGetSymbolAddress(&pv, g_v);
    cudaGetSymbolAddress(&psim, g_sim);
    cudaGetSymbolAddress(&psim2, g_sim2);
    cudaGetSymbolAddress(&pouth, g_outh);
    cudaGetSymbolAddress(&pvg, g_vg);
    cudaGetSymbolAddress(&pgated, g_gated);

    dim3 gBig(16, 16, 1);      // 2048x2048 output tiles

    rope_cs_kernel<<<NN * DHH / 256, 256>>>(rf);

    // QKV projections (tf32 tensor cores)
    gemm_tf32<<<gBig, 256>>>(x, DIMM, 0, 0, wq, HD, 0, 0, (float*)pq, HD, 0, 0,
                             TT, HD, DIMM, 0, nullptr, 1.f);
    gemm_tf32<<<gBig, 256>>>(x, DIMM, 0, 0, wk, HD, 0, 0, (float*)pk, HD, 0, 0,
                             TT, HD, DIMM, 0, nullptr, 1.f);
    gemm_tf32<<<gBig, 256>>>(x, DIMM, 0, 0, wv, HD, 0, 0, (float*)pv, HD, 0, 0,
                             TT, HD, DIMM, 0, nullptr, 1.f);

    norm_rot2_kernel<<<8192, 256>>>(cope);

    // sim = 10 * Q @ K^T  (causal tiles only)
    gemm_tf32<<<dim3(8, 8, BB * HH), 256>>>(
        (float*)pq, HD, (long long)NN * HD, DHH,
        (float*)pk, HD, (long long)NN * HD, DHH,
        (float*)psim, NN, 16LL * NN * NN, (long long)NN * NN,
        NN, NN, DHH, 1 | 2, nullptr, 10.0f);

    mix_heads_kernel<<<dim3(4, NN, BB), 256>>>(thp);      // g_sim -> g_sim2
    cope_softmax_kernel<<<dim3(NN, HH, BB), 256>>>();     // g_sim2 -> attn in g_sim
    mix_heads_kernel<<<dim3(4, NN, BB), 256>>>(tho);      // g_sim -> g_sim2

    // out = attn2 @ V (causal A mask, triangular K)
    gemm_tf32<<<dim3(1, 8, BB * HH), 256>>>(
        (float*)psim2, NN, 16LL * NN * NN, (long long)NN * NN,
        (float*)pv, HD, (long long)NN * HD, DHH,
        (float*)pouth, DHH, 16LL * NN * DHH, (long long)NN * DHH,
        NN, DHH, NN, 4, nullptr, 1.f);

    hgate_kernel<<<TT, 512>>>(x, whg, bhg);
    gemm_tf32<<<gBig, 256>>>(x, DIMM, 0, 0, wvg, HD, 0, 0, (float*)pvg, HD, 0, 0,
                             TT, HD, DIMM, 8, bvg, 1.f);
    gate_mul_kernel<<<(TT * HD) / 256, 256>>>();

    gemm_tf32<<<gBig, 256>>>((float*)pgated, HD, 0, 0, wout, DIMM, 0, 0, out, DIMM, 0, 0,
                             TT, DIMM, HD, 0, nullptr, 1.f);
}

// round 7
// speedup vs baseline: 3.0589x; 1.5292x over previous
#include <cuda_runtime.h>
#include <math.h>

#define BB   2
#define NN   1024
#define DIMM 2048
#define HH   16
#define DHH  128
#define TT   (BB*NN)    // 2048 tokens
#define HD   (HH*DHH)   // 2048
#define MAXP 16
#define NEGV -1e30f

#define STAGES 3
#define ASTR   36            // A / B-trans smem row stride (floats)
#define BKSTR  136           // B k-major smem row stride (floats)
#define STAGE_A (128*ASTR)   // 4608 floats
#define STAGE_B 4608         // max(128*36, 32*136)
#define SMEM_BYTES (STAGES*(STAGE_A+STAGE_B)*4)   // 110592 B

// ---------------- scratch (device globals; zero-init, no allocs) ----------------
__device__ __align__(256) float g_q[TT*HD];
__device__ __align__(256) float g_k[TT*HD];
__device__ __align__(256) float g_v[TT*HD];
__device__ __align__(256) float g_sim [BB*HH*NN*NN];   // scores / attn (ping)
__device__ __align__(256) float g_sim2[BB*HH*NN*NN];   // mixed scores / mixed attn (pong)
__device__ __align__(256) float g_logits[BB*HH*NN*MAXP];
__device__ __align__(256) float g_outh[BB*HH*NN*DHH];
__device__ __align__(256) float g_vg[TT*HD];
__device__ __align__(256) float g_hg[TT*HH];
__device__ __align__(256) float g_gated[TT*HD];
__device__ __align__(256) float g_cos[NN*DHH];
__device__ __align__(256) float g_sin[NN*DHH];

__device__ __forceinline__ float sigmoidf_(float x) { return 1.0f / (1.0f + expf(-x)); }

__device__ __forceinline__ unsigned f2tf(float x) {
    unsigned u; asm("cvt.rna.tf32.f32 %0, %1;" : "=r"(u) : "f"(x)); return u;
}

__device__ __forceinline__ void cpa16(float* dst, const float* src) {
    unsigned d = (unsigned)__cvta_generic_to_shared(dst);
    asm volatile("cp.async.cg.shared.global [%0], [%1], 16;" :: "r"(d), "l"(src));
}

#define MMA_TF32(cc, aa, bb)                                                     \
    asm volatile("mma.sync.aligned.m16n8k8.row.col.f32.tf32.tf32.f32 "           \
                 "{%0,%1,%2,%3},{%4,%5,%6,%7},{%8,%9},{%0,%1,%2,%3};"            \
                 : "+f"((cc)[0]), "+f"((cc)[1]), "+f"((cc)[2]), "+f"((cc)[3])    \
                 : "r"((aa)[0]), "r"((aa)[1]), "r"((aa)[2]), "r"((aa)[3]),       \
                   "r"((bb)[0]), "r"((bb)[1]))

// =====================================================================
// tf32 tensor-core GEMM, 3-stage cp.async pipeline.
//   C[M,N] = scale * A[M,K] @ B[K,N]   (+ optional sigmoid(·+bias) epilogue)
// flags: 1 = transB (B[k][n] = Bsrc[n*ldb + k])
//        2 = causal block skip (skip tiles with jt > it)
//        4 = triangular K bound (kmax = row0+128); A's upper band must be 0
//        8 = sigmoid(acc + bias[col]) epilogue
// Block: 256 threads; tile 128x128x32; warp tile 64x32 (2x4 warps).
// =====================================================================
__global__ __launch_bounds__(256, 2) void gemm_tf32(
    const float* __restrict__ A, int lda, long long sAb, long long sAh,
    const float* __restrict__ B, int ldb, long long sBb, long long sBh,
    float* __restrict__ C, int ldc, long long sCb, long long sCh,
    int M, int N, int K, int flags, const float* __restrict__ bias, float scale)
{
    if ((flags & 2) && blockIdx.x > blockIdx.y) return;
    int z = blockIdx.z, bz = z >> 4, hz = z & 15;
    const float* Ab = A + bz * sAb + hz * sAh;
    const float* Bb = B + bz * sBb + hz * sBh;
    float*       Cb = C + bz * sCb + hz * sCh;

    extern __shared__ float sm[];
    float* Asm = sm;
    float* Bsm = sm + STAGES * STAGE_A;

    const int tid = threadIdx.x, lane = tid & 31, wid = tid >> 5;
    const int wm = wid >> 2, wn = wid & 3;
    const int g = lane >> 2, tg = lane & 3;
    const int row0 = blockIdx.y * 128, col0 = blockIdx.x * 128;
    const bool tB = (flags & 1) != 0;

    float c[4][4][4];
#pragma unroll
    for (int mt = 0; mt < 4; mt++)
#pragma unroll
        for (int nt = 0; nt < 4; nt++)
#pragma unroll
            for (int e = 0; e < 4; e++) c[mt][nt][e] = 0.f;

    int kmax = K;
    if (flags & 4) { int t = row0 + 128; if (t < kmax) kmax = t; }
    const int niter = kmax >> 5;

    auto load_stage = [&](int s, int k0) {
        float* as = Asm + s * STAGE_A;
#pragma unroll
        for (int i = 0; i < 4; i++) {
            int chunk = i * 256 + tid;
            int r = chunk >> 3, seg = (chunk & 7) << 2;
            cpa16(as + r * ASTR + seg, Ab + (size_t)(row0 + r) * lda + k0 + seg);
        }
        float* bs = Bsm + s * STAGE_B;
        if (tB) {
#pragma unroll
            for (int i = 0; i < 4; i++) {
                int chunk = i * 256 + tid;
                int r = chunk >> 3, seg = (chunk & 7) << 2;
                cpa16(bs + r * ASTR + seg, Bb + (size_t)(col0 + r) * ldb + k0 + seg);
            }
        } else {
#pragma unroll
            for (int i = 0; i < 4; i++) {
                int chunk = i * 256 + tid;
                int kk = chunk >> 5, seg = (chunk & 31) << 2;
                cpa16(bs + kk * BKSTR + seg, Bb + (size_t)(k0 + kk) * ldb + col0 + seg);
            }
        }
    };

    auto compute_stage = [&](int s) {
        const float* as = Asm + s * STAGE_A;
        const float* bs = Bsm + s * STAGE_B;
#pragma unroll
        for (int ks = 0; ks < 4; ks++) {
            int kb = ks * 8;
            unsigned a[4][4], b[4][2];
#pragma unroll
            for (int mt = 0; mt < 4; mt++) {
                int m = wm * 64 + mt * 16 + g;
                a[mt][0] = f2tf(as[m * ASTR + kb + tg]);
                a[mt][1] = f2tf(as[(m + 8) * ASTR + kb + tg]);
                a[mt][2] = f2tf(as[m * ASTR + kb + tg + 4]);
                a[mt][3] = f2tf(as[(m + 8) * ASTR + kb + tg + 4]);
            }
            if (tB) {
#pragma unroll
                for (int nt = 0; nt < 4; nt++) {
                    int n = wn * 32 + nt * 8 + g;
                    b[nt][0] = f2tf(bs[n * ASTR + kb + tg]);
                    b[nt][1] = f2tf(bs[n * ASTR + kb + tg + 4]);
                }
            } else {
#pragma unroll
                for (int nt = 0; nt < 4; nt++) {
                    int n = wn * 32 + nt * 8 + g;
                    b[nt][0] = f2tf(bs[(kb + tg) * BKSTR + n]);
                    b[nt][1] = f2tf(bs[(kb + tg + 4) * BKSTR + n]);
                }
            }
#pragma unroll
            for (int mt = 0; mt < 4; mt++)
#pragma unroll
                for (int nt = 0; nt < 4; nt++)
                    MMA_TF32(c[mt][nt], a[mt], b[nt]);
        }
    };

    // ---- pipeline prologue ----
#pragma unroll
    for (int s = 0; s < STAGES - 1; s++) {
        if (s < niter) load_stage(s, s * 32);
        asm volatile("cp.async.commit_group;");
    }
    // ---- mainloop ----
    for (int it = 0; it < niter; it++) {
        asm volatile("cp.async.wait_group %0;" :: "n"(STAGES - 2));
        __syncthreads();
        int nxt = it + STAGES - 1;
        if (nxt < niter) load_stage(nxt % STAGES, nxt * 32);
        asm volatile("cp.async.commit_group;");
        compute_stage(it % STAGES);
    }

    // ---- epilogue ----
#pragma unroll
    for (int mt = 0; mt < 4; mt++) {
        int r0 = row0 + wm * 64 + mt * 16 + g;
#pragma unroll
        for (int nt = 0; nt < 4; nt++) {
            int col = col0 + wn * 32 + nt * 8 + 2 * tg;
            float v0 = c[mt][nt][0] * scale, v1 = c[mt][nt][1] * scale;
            float v2 = c[mt][nt][2] * scale, v3 = c[mt][nt][3] * scale;
            if (flags & 8) {
                v0 = sigmoidf_(v0 + bias[col]);     v1 = sigmoidf_(v1 + bias[col + 1]);
                v2 = sigmoidf_(v2 + bias[col]);     v3 = sigmoidf_(v3 + bias[col + 1]);
            }
            float2 p0; p0.x = v0; p0.y = v1;
            float2 p1; p1.x = v2; p1.y = v3;
            *(float2*)(Cb + (size_t)r0 * ldc + col)       = p0;
            *(float2*)(Cb + (size_t)(r0 + 8) * ldc + col) = p1;
        }
    }
}

// ---------------- rope table: cos/sin of rotary_freqs ----------------
__global__ void rope_cs_kernel(const float* __restrict__ rf) {
    int idx = blockIdx.x * 256 + threadIdx.x;
    float f = rf[idx];
    g_cos[idx] = cosf(f);
    g_sin[idx] = sinf(f);
}

// ---------------- warp-per-vector L2-norm + rotary (+ CoPE logits for q) ----------
__global__ void norm_rot2_kernel(const float* __restrict__ cope) {
    int lane = threadIdx.x & 31;
    int w = blockIdx.x * 8 + (threadIdx.x >> 5);
    const int NV = TT * HH;
    int isK = (w >= NV) ? 1 : 0;
    int vec = isK ? (w - NV) : w;
    int token = vec >> 4, h = vec & 15;
    int n = token & (NN - 1), b = token >> 10;

    float* ptr = (isK ? g_k : g_q) + (size_t)token * HD + h * DHH + lane * 4;
    float4 v = *(float4*)ptr;
    float ss = v.x * v.x + v.y * v.y + v.z * v.z + v.w * v.w;
#pragma unroll
    for (int o = 16; o > 0; o >>= 1) ss += __shfl_xor_sync(0xffffffffu, ss, o);
    float inv = 1.0f / fmaxf(sqrtf(ss), 1e-12f);
    v.x *= inv; v.y *= inv; v.z *= inv; v.w *= inv;

    float4 cs = *(const float4*)(g_cos + n * DHH + lane * 4);
    float4 sn = *(const float4*)(g_sin + n * DHH + lane * 4);
    float4 o;
    o.x = v.x * cs.x - v.y * sn.x;
    o.y = v.y * cs.y + v.x * sn.y;
    o.z = v.z * cs.z - v.w * sn.z;
    o.w = v.w * cs.w + v.z * sn.w;
    *(float4*)ptr = o;

    if (!isK) {
        float myv = 0.f;
#pragma unroll
        for (int p = 0; p < MAXP; p++) {
            float4 cp = *(const float4*)(cope + p * DHH + lane * 4);
            float pa = o.x * cp.x + o.y * cp.y + o.z * cp.z + o.w * cp.w;
#pragma unroll
            for (int off = 16; off > 0; off >>= 1)
                pa += __shfl_xor_sync(0xffffffffu, pa, off);
            if (lane == p) myv = pa;
        }
        if (lane < MAXP)
            g_logits[((size_t)(b * HH + h) * NN + n) * MAXP + lane] = myv;
    }
}

// ---------------- talking-heads mix (j<=i only) ----------------
__global__ void mix_heads_kernel(const float* __restrict__ th) {
    int i = blockIdx.y, b = blockIdx.z;
    if ((int)(blockIdx.x * 256) > i) return;
    __shared__ float sth[256];
    sth[threadIdx.x] = th[threadIdx.x];
    __syncthreads();
    int j = blockIdx.x * 256 + threadIdx.x;
    if (j > i) return;
    size_t base = ((size_t)b * HH * NN + i) * NN + j;
    float vals[16];
#pragma unroll
    for (int g = 0; g < 16; g++) vals[g] = g_sim[base + (size_t)g * NN * NN];
#pragma unroll
    for (int h = 0; h < 16; h++) {
        float s = 0.f;
#pragma unroll
        for (int g = 0; g < 16; g++) s = fmaf(sth[h * 16 + g], vals[g], s);
        g_sim2[base + (size_t)h * NN * NN] = s;
    }
}

// ---------------- CoPE + softmax per row ----------------
__global__ void cope_softmax_kernel() {
    int i = blockIdx.x, h = blockIdx.y, b = blockIdx.z;
    int tid = threadIdx.x;
    size_t rowbase = (((size_t)(b * HH + h)) * NN + i) * NN;

    __shared__ float lrow[MAXP];
    __shared__ float wsum[8], woff[8];
    __shared__ float s_total, s_m, s_sum;

    if (tid < MAXP)
        lrow[tid] = g_logits[(((size_t)(b * HH + h)) * NN + i) * MAXP + tid];

    int j0 = tid * 4;
    float v[4], g[4];
#pragma unroll
    for (int c = 0; c < 4; c++) {
        int j = j0 + c;
        if (j <= i) { v[c] = g_sim2[rowbase + j]; g[c] = sigmoidf_(v[c]); }
        else        { v[c] = NEGV;               g[c] = 0.f; }
    }
    float lp[4];
    lp[0] = 0.f; lp[1] = g[0]; lp[2] = lp[1] + g[1]; lp[3] = lp[2] + g[2];
    float tsum = lp[3] + g[3];

    unsigned lane = tid & 31, wid = tid >> 5;
    float incl = tsum;
#pragma unroll
    for (int o = 1; o < 32; o <<= 1) {
        float t = __shfl_up_sync(0xffffffffu, incl, o);
        if (lane >= o) incl += t;
    }
    if (lane == 31) wsum[wid] = incl;
    __syncthreads();
    if (tid == 0) {
        float run = 0.f;
        for (int w = 0; w < 8; w++) { woff[w] = run; run += wsum[w]; }
        s_total = run;
    }
    __syncthreads();
    float basex = (incl - tsum) + woff[wid];
    float total = s_total;

    float nv[4];
#pragma unroll
    for (int c = 0; c < 4; c++) {
        int j = j0 + c;
        if (j <= i) {
            float pos = total - (basex + lp[c]);
            pos = fminf(fmaxf(pos, 0.f), 15.0f);
            float pf = floorf(pos);
            float w  = pos - pf;
            int fi = (int)pf;
            int ci = (int)ceilf(pos);
            nv[c] = v[c] + lrow[ci] * w + lrow[fi] * (1.0f - w);
        } else nv[c] = NEGV;
    }
    float m = fmaxf(fmaxf(nv[0], nv[1]), fmaxf(nv[2], nv[3]));
#pragma unroll
    for (int o = 16; o > 0; o >>= 1) m = fmaxf(m, __shfl_xor_sync(0xffffffffu, m, o));
    if (lane == 0) wsum[wid] = m;
    __syncthreads();
    if (tid == 0) {
        float mm = wsum[0];
        for (int w = 1; w < 8; w++) mm = fmaxf(mm, wsum[w]);
        s_m = mm;
    }
    __syncthreads();
    m = s_m;
    float e[4]; float ls = 0.f;
#pragma unroll
    for (int c = 0; c < 4; c++) { e[c] = expf(nv[c] - m); ls += e[c]; }
#pragma unroll
    for (int o = 16; o > 0; o >>= 1) ls += __shfl_xor_sync(0xffffffffu, ls, o);
    if (lane == 0) woff[wid] = ls;
    __syncthreads();
    if (tid == 0) {
        float t = 0.f;
        for (int w = 0; w < 8; w++) t += woff[w];
        s_sum = t;
    }
    __syncthreads();
    float invs = 1.0f / s_sum;
#pragma unroll
    for (int c = 0; c < 4; c++) {
        int j = j0 + c;
        if (j <= i) g_sim[rowbase + j] = e[c] * invs;
    }
}

// ---------------- head gate ----------------
__global__ void hgate_kernel(const float* __restrict__ x, const float* __restrict__ wh,
                             const float* __restrict__ bh) {
    int token = blockIdx.x;
    __shared__ __align__(16) float sx[DIMM];
    int tid = threadIdx.x;
    *(float4*)&sx[tid * 4] = *(const float4*)&x[(size_t)token * DIMM + tid * 4];
    __syncthreads();
    int h = tid >> 5, lane = tid & 31;
    float s = 0.f;
    for (int e = lane; e < DIMM; e += 32) s = fmaf(sx[e], wh[e * HH + h], s);
#pragma unroll
    for (int o = 16; o > 0; o >>= 1) s += __shfl_xor_sync(0xffffffffu, s, o);
    if (lane == 0) g_hg[token * HH + h] = sigmoidf_(s + bh[h]);
}

// ---------------- apply gates, merge heads ----------------
__global__ void gate_mul_kernel() {
    int idx = blockIdx.x * 256 + threadIdx.x;
    int token = idx >> 11;
    int c = idx & 2047;
    int h = c >> 7, d = c & 127;
    int b = token >> 10, n = token & 1023;
    float o = g_outh[(((size_t)(b * HH + h)) * NN + n) * DHH + d];
    g_gated[idx] = o * g_hg[token * HH + h] * g_vg[idx];
}

// ---------------- launch ----------------
extern "C" void kernel_launch(void* const* d_in, const int* in_sizes, int n_in,
                              void* d_out, int out_size) {
    const float* x    = (const float*)d_in[0];
    const float* rf   = (const float*)d_in[1];
    const float* wq   = (const float*)d_in[2];
    const float* wk   = (const float*)d_in[3];
    const float* wv   = (const float*)d_in[4];
    const float* cope = (const float*)d_in[5];
    const float* thp  = (const float*)d_in[6];
    const float* tho  = (const float*)d_in[7];
    const float* wvg  = (const float*)d_in[8];
    const float* bvg  = (const float*)d_in[9];
    const float* whg  = (const float*)d_in[10];
    const float* bhg  = (const float*)d_in[11];
    const float* wout = (const float*)d_in[12];
    float* out = (float*)d_out;

    cudaFuncSetAttribute(gemm_tf32, cudaFuncAttributeMaxDynamicSharedMemorySize, SMEM_BYTES);

    void *pq, *pk, *pv, *psim, *psim2, *pouth, *pvg, *pgated;
    cudaGetSymbolAddress(&pq, g_q);
    cudaGetSymbolAddress(&pk, g_k);
    cudaGetSymbolAddress(&pv, g_v);
    cudaGetSymbolAddress(&psim, g_sim);
    cudaGetSymbolAddress(&psim2, g_sim2);
    cudaGetSymbolAddress(&pouth, g_outh);
    cudaGetSymbolAddress(&pvg, g_vg);
    cudaGetSymbolAddress(&pgated, g_gated);

    dim3 gBig(16, 16, 1);      // 2048x2048 output tiles

    rope_cs_kernel<<<NN * DHH / 256, 256>>>(rf);

    // QKV projections (tf32 tensor cores, pipelined)
    gemm_tf32<<<gBig, 256, SMEM_BYTES>>>(x, DIMM, 0, 0, wq, HD, 0, 0, (float*)pq, HD, 0, 0,
                                         TT, HD, DIMM, 0, nullptr, 1.f);
    gemm_tf32<<<gBig, 256, SMEM_BYTES>>>(x, DIMM, 0, 0, wk, HD, 0, 0, (float*)pk, HD, 0, 0,
                                         TT, HD, DIMM, 0, nullptr, 1.f);
    gemm_tf32<<<gBig, 256, SMEM_BYTES>>>(x, DIMM, 0, 0, wv, HD, 0, 0, (float*)pv, HD, 0, 0,
                                         TT, HD, DIMM, 0, nullptr, 1.f);

    norm_rot2_kernel<<<8192, 256>>>(cope);

    // sim = 10 * Q @ K^T  (causal tiles only, transB)
    gemm_tf32<<<dim3(8, 8, BB * HH), 256, SMEM_BYTES>>>(
        (float*)pq, HD, (long long)NN * HD, DHH,
        (float*)pk, HD, (long long)NN * HD, DHH,
        (float*)psim, NN, 16LL * NN * NN, (long long)NN * NN,
        NN, NN, DHH, 1 | 2, nullptr, 10.0f);

    mix_heads_kernel<<<dim3(4, NN, BB), 256>>>(thp);      // g_sim -> g_sim2
    cope_softmax_kernel<<<dim3(NN, HH, BB), 256>>>();     // g_sim2 -> attn in g_sim
    mix_heads_kernel<<<dim3(4, NN, BB), 256>>>(tho);      // g_sim -> g_sim2

    // out = attn2 @ V (triangular K; upper band of g_sim2 is provably zero)
    gemm_tf32<<<dim3(1, 8, BB * HH), 256, SMEM_BYTES>>>(
        (float*)psim2, NN, 16LL * NN * NN, (long long)NN * NN,
        (float*)pv, HD, (long long)NN * HD, DHH,
        (float*)pouth, DHH, 16LL * NN * DHH, (long long)NN * DHH,
        NN, DHH, NN, 4, nullptr, 1.f);

    hgate_kernel<<<TT, 512>>>(x, whg, bhg);
    gemm_tf32<<<gBig, 256, SMEM_BYTES>>>(x, DIMM, 0, 0, wvg, HD, 0, 0, (float*)pvg, HD, 0, 0,
                                         TT, HD, DIMM, 8, bvg, 1.f);
    gate_mul_kernel<<<(TT * HD) / 256, 256>>>();

    gemm_tf32<<<gBig, 256, SMEM_BYTES>>>((float*)pgated, HD, 0, 0, wout, DIMM, 0, 0,
                                         out, DIMM, 0, 0, TT, DIMM, HD, 0, nullptr, 1.f);
}

// round 8
// speedup vs baseline: 3.4606x; 1.1313x over previous
#include <cuda_runtime.h>
#include <math.h>

#define BB   2
#define NN   1024
#define DIMM 2048
#define HH   16
#define DHH  128
#define TT   (BB*NN)    // 2048 tokens
#define HD   (HH*DHH)   // 2048
#define MAXP 16
#define NEGV -1e30f

#define STAGES 3
#define ASTR   36                  // smem row stride (floats)
#define STAGE  (128*ASTR)          // 4608 floats per tile per stage
#define SMEM_BYTES (STAGES*2*STAGE*4)   // 110592 B

// ---------------- scratch (device globals; zero-init, no allocs) ----------------
__device__ __align__(256) float g_q[TT*HD];
__device__ __align__(256) float g_k[TT*HD];
__device__ __align__(256) float g_v[TT*HD];
__device__ __align__(256) float g_vt[TT*HD];           // V transposed per batch: [b][c][n]
__device__ __align__(256) float g_sim [BB*HH*NN*NN];   // scores / attn (ping)
__device__ __align__(256) float g_sim2[BB*HH*NN*NN];   // mixed scores / mixed attn (pong)
__device__ __align__(256) float g_logits[BB*HH*NN*MAXP];
__device__ __align__(256) float g_outh[BB*HH*NN*DHH];
__device__ __align__(256) float g_vg[TT*HD];
__device__ __align__(256) float g_hg[TT*HH];
__device__ __align__(256) float g_gated[TT*HD];
__device__ __align__(256) float g_cos[NN*DHH];
__device__ __align__(256) float g_sin[NN*DHH];
__device__ __align__(256) float g_xr[TT*DIMM];         // x rounded to tf32
__device__ __align__(256) float g_wqT [DIMM*HD];
__device__ __align__(256) float g_wkT [DIMM*HD];
__device__ __align__(256) float g_wvT [DIMM*HD];
__device__ __align__(256) float g_wvgT[DIMM*HD];
__device__ __align__(256) float g_woutT[HD*DIMM];

__device__ __forceinline__ float sigmoidf_(float x) { return 1.0f / (1.0f + expf(-x)); }

__device__ __forceinline__ unsigned f2tf(float x) {
    unsigned u; asm("cvt.rna.tf32.f32 %0, %1;" : "=r"(u) : "f"(x)); return u;
}
__device__ __forceinline__ float tf32r(float x) { return __uint_as_float(f2tf(x)); }

__device__ __forceinline__ void cpa16(float* dst, const float* src) {
    unsigned d = (unsigned)__cvta_generic_to_shared(dst);
    asm volatile("cp.async.cg.shared.global [%0], [%1], 16;" :: "r"(d), "l"(src));
}

__device__ __forceinline__ void ldsm4(unsigned& r0, unsigned& r1, unsigned& r2, unsigned& r3,
                                      const float* p) {
    unsigned a = (unsigned)__cvta_generic_to_shared(p);
    asm volatile("ldmatrix.sync.aligned.m8n8.x4.shared.b16 {%0,%1,%2,%3}, [%4];"
                 : "=r"(r0), "=r"(r1), "=r"(r2), "=r"(r3) : "r"(a));
}

#define MMA_TF32(cc, aa, bb)                                                     \
    asm volatile("mma.sync.aligned.m16n8k8.row.col.f32.tf32.tf32.f32 "           \
                 "{%0,%1,%2,%3},{%4,%5,%6,%7},{%8,%9},{%0,%1,%2,%3};"            \
                 : "+f"((cc)[0]), "+f"((cc)[1]), "+f"((cc)[2]), "+f"((cc)[3])    \
                 : "r"((aa)[0]), "r"((aa)[1]), "r"((aa)[2]), "r"((aa)[3]),       \
                   "r"((bb)[0]), "r"((bb)[1]))

// =====================================================================
// tf32 tensor-core GEMM. Operands MUST be pre-rounded to tf32 in gmem.
//   C[M,N] = scale * A[M,K] @ B^T  where B is stored [N][K] row-major.
// flags: 2 = causal block skip; 4 = triangular K bound (kmax=row0+128,
//        A upper band must be zero); 8 = sigmoid(acc+bias[col]) epilogue.
// 256 threads; tile 128x128x32; warp tile 64x32 (2x4 warps); 3-stage cp.async;
// fragments via ldmatrix (no cvt, no scalar LDS in mainloop).
// =====================================================================
__global__ __launch_bounds__(256, 2) void gemm_tc(
    const float* __restrict__ A, int lda, long long sAb, long long sAh,
    const float* __restrict__ B, int ldb, long long sBb, long long sBh,
    float* __restrict__ C, int ldc, long long sCb, long long sCh,
    int K, int flags, const float* __restrict__ bias, float scale)
{
    if ((flags & 2) && blockIdx.x > blockIdx.y) return;
    int z = blockIdx.z, bz = z >> 4, hz = z & 15;
    const float* Ab = A + bz * sAb + hz * sAh;
    const float* Bb = B + bz * sBb + hz * sBh;
    float*       Cb = C + bz * sCb + hz * sCh;

    extern __shared__ float sm[];
    float* Asm = sm;
    float* Bsm = sm + STAGES * STAGE;

    const int tid = threadIdx.x, lane = tid & 31, wid = tid >> 5;
    const int wm = wid >> 2, wn = wid & 3;
    const int g = lane >> 2, tg = lane & 3;
    const int row0 = blockIdx.y * 128, col0 = blockIdx.x * 128;

    float c[4][4][4];
#pragma unroll
    for (int mt = 0; mt < 4; mt++)
#pragma unroll
        for (int nt = 0; nt < 4; nt++)
#pragma unroll
            for (int e = 0; e < 4; e++) c[mt][nt][e] = 0.f;

    int kmax = K;
    if (flags & 4) { int t = row0 + 128; if (t < kmax) kmax = t; }
    const int niter = kmax >> 5;

    // ldmatrix source addresses (stage-0 base)
    const int a_rl = (lane & 7) + ((lane >> 3) & 1) * 8;
    const int a_ko = (lane >> 4) * 4;
    const int b_rl = (lane & 7) + ((lane >> 4) & 1) * 8;
    const int b_ko = ((lane >> 3) & 1) * 4;
    const float* aF[4]; const float* bF[2];
#pragma unroll
    for (int mt = 0; mt < 4; mt++)
        aF[mt] = Asm + (wm * 64 + mt * 16 + a_rl) * ASTR + a_ko;
#pragma unroll
    for (int p = 0; p < 2; p++)
        bF[p] = Bsm + (wn * 32 + p * 16 + b_rl) * ASTR + b_ko;

    auto load_stage = [&](int s, int k0) {
        float* as = Asm + s * STAGE;
        float* bs = Bsm + s * STAGE;
#pragma unroll
        for (int i = 0; i < 4; i++) {
            int chunk = i * 256 + tid;
            int r = chunk >> 3, seg = (chunk & 7) << 2;
            cpa16(as + r * ASTR + seg, Ab + (size_t)(row0 + r) * lda + k0 + seg);
            cpa16(bs + r * ASTR + seg, Bb + (size_t)(col0 + r) * ldb + k0 + seg);
        }
    };

    auto compute_stage = [&](int s) {
        const int off = s * STAGE;
#pragma unroll
        for (int ks = 0; ks < 4; ks++) {
            const int kb = ks * 8;
            unsigned a[4][4], b[4][2];
#pragma unroll
            for (int mt = 0; mt < 4; mt++)
                ldsm4(a[mt][0], a[mt][1], a[mt][2], a[mt][3], aF[mt] + off + kb);
#pragma unroll
            for (int p = 0; p < 2; p++) {
                unsigned t0, t1, t2, t3;
                ldsm4(t0, t1, t2, t3, bF[p] + off + kb);
                b[2 * p][0] = t0; b[2 * p][1] = t1;
                b[2 * p + 1][0] = t2; b[2 * p + 1][1] = t3;
            }
#pragma unroll
            for (int mt = 0; mt < 4; mt++)
#pragma unroll
                for (int nt = 0; nt < 4; nt++)
                    MMA_TF32(c[mt][nt], a[mt], b[nt]);
        }
    };

    // pipeline
#pragma unroll
    for (int s = 0; s < STAGES - 1; s++) {
        if (s < niter) load_stage(s, s * 32);
        asm volatile("cp.async.commit_group;");
    }
    for (int it = 0; it < niter; it++) {
        asm volatile("cp.async.wait_group %0;" :: "n"(STAGES - 2));
        __syncthreads();
        int nxt = it + STAGES - 1;
        if (nxt < niter) load_stage(nxt % STAGES, nxt * 32);
        asm volatile("cp.async.commit_group;");
        compute_stage(it % STAGES);
    }

    // epilogue
#pragma unroll
    for (int mt = 0; mt < 4; mt++) {
        int r0 = row0 + wm * 64 + mt * 16 + g;
#pragma unroll
        for (int nt = 0; nt < 4; nt++) {
            int col = col0 + wn * 32 + nt * 8 + 2 * tg;
            float v0 = c[mt][nt][0] * scale, v1 = c[mt][nt][1] * scale;
            float v2 = c[mt][nt][2] * scale, v3 = c[mt][nt][3] * scale;
            if (flags & 8) {
                v0 = sigmoidf_(v0 + bias[col]);     v1 = sigmoidf_(v1 + bias[col + 1]);
                v2 = sigmoidf_(v2 + bias[col]);     v3 = sigmoidf_(v3 + bias[col + 1]);
            }
            float2 p0; p0.x = v0; p0.y = v1;
            float2 p1; p1.x = v2; p1.y = v3;
            *(float2*)(Cb + (size_t)r0 * ldc + col)       = p0;
            *(float2*)(Cb + (size_t)(r0 + 8) * ldc + col) = p1;
        }
    }
}

// ---------------- transpose + tf32 round: out[c][r] = tf32(in[r][c]) ----------------
__global__ void transpose_round(const float* __restrict__ in, float* __restrict__ out,
                                int rows, int cols, long long inz, long long outz) {
    __shared__ float t[32][33];
    const float* ip = in + blockIdx.z * inz;
    float* op = out + blockIdx.z * outz;
    int c0 = blockIdx.x * 32, r0 = blockIdx.y * 32;
    int tx = threadIdx.x, ty = threadIdx.y;   // 32 x 8
#pragma unroll
    for (int i = 0; i < 32; i += 8)
        t[ty + i][tx] = ip[(size_t)(r0 + ty + i) * cols + c0 + tx];
    __syncthreads();
#pragma unroll
    for (int i = 0; i < 32; i += 8)
        op[(size_t)(c0 + ty + i) * rows + r0 + tx] = tf32r(t[tx][ty + i]);
}

// ---------------- tf32 round copy (x -> g_xr) ----------------
__global__ void round_copy(const float* __restrict__ in, float* __restrict__ out) {
    int i = (blockIdx.x * 256 + threadIdx.x) * 4;
    float4 v = *(const float4*)(in + i);
    v.x = tf32r(v.x); v.y = tf32r(v.y); v.z = tf32r(v.z); v.w = tf32r(v.w);
    *(float4*)(out + i) = v;
}

// ---------------- rope table ----------------
__global__ void rope_cs_kernel(const float* __restrict__ rf) {
    int idx = blockIdx.x * 256 + threadIdx.x;
    float f = rf[idx];
    g_cos[idx] = cosf(f);
    g_sin[idx] = sinf(f);
}

// ---------------- warp-per-vector L2-norm + rotary (+ CoPE logits for q) ----------
// stores tf32-rounded q/k (GEMM operands); logits use full precision.
__global__ void norm_rot2_kernel(const float* __restrict__ cope) {
    int lane = threadIdx.x & 31;
    int w = blockIdx.x * 8 + (threadIdx.x >> 5);
    const int NV = TT * HH;
    int isK = (w >= NV) ? 1 : 0;
    int vec = isK ? (w - NV) : w;
    int token = vec >> 4, h = vec & 15;
    int n = token & (NN - 1), b = token >> 10;

    float* ptr = (isK ? g_k : g_q) + (size_t)token * HD + h * DHH + lane * 4;
    float4 v = *(float4*)ptr;
    float ss = v.x * v.x + v.y * v.y + v.z * v.z + v.w * v.w;
#pragma unroll
    for (int o = 16; o > 0; o >>= 1) ss += __shfl_xor_sync(0xffffffffu, ss, o);
    float inv = 1.0f / fmaxf(sqrtf(ss), 1e-12f);
    v.x *= inv; v.y *= inv; v.z *= inv; v.w *= inv;

    float4 cs = *(const float4*)(g_cos + n * DHH + lane * 4);
    float4 sn = *(const float4*)(g_sin + n * DHH + lane * 4);
    float4 o;
    o.x = v.x * cs.x - v.y * sn.x;
    o.y = v.y * cs.y + v.x * sn.y;
    o.z = v.z * cs.z - v.w * sn.z;
    o.w = v.w * cs.w + v.z * sn.w;
    float4 orr;
    orr.x = tf32r(o.x); orr.y = tf32r(o.y); orr.z = tf32r(o.z); orr.w = tf32r(o.w);
    *(float4*)ptr = orr;

    if (!isK) {
        float myv = 0.f;
#pragma unroll
        for (int p = 0; p < MAXP; p++) {
            float4 cp = *(const float4*)(cope + p * DHH + lane * 4);
            float pa = o.x * cp.x + o.y * cp.y + o.z * cp.z + o.w * cp.w;
#pragma unroll
            for (int off = 16; off > 0; off >>= 1)
                pa += __shfl_xor_sync(0xffffffffu, pa, off);
            if (lane == p) myv = pa;
        }
        if (lane < MAXP)
            g_logits[((size_t)(b * HH + h) * NN + n) * MAXP + lane] = myv;
    }
}

// ---------------- talking-heads mix (j<=i only); rnd=1 rounds stores to tf32 ------
__global__ void mix_heads_kernel(const float* __restrict__ th, int rnd) {
    int i = blockIdx.y, b = blockIdx.z;
    if ((int)(blockIdx.x * 256) > i) return;
    __shared__ float sth[256];
    sth[threadIdx.x] = th[threadIdx.x];
    __syncthreads();
    int j = blockIdx.x * 256 + threadIdx.x;
    if (j > i) return;
    size_t base = ((size_t)b * HH * NN + i) * NN + j;
    float vals[16];
#pragma unroll
    for (int g = 0; g < 16; g++) vals[g] = g_sim[base + (size_t)g * NN * NN];
#pragma unroll
    for (int h = 0; h < 16; h++) {
        float s = 0.f;
#pragma unroll
        for (int g = 0; g < 16; g++) s = fmaf(sth[h * 16 + g], vals[g], s);
        g_sim2[base + (size_t)h * NN * NN] = rnd ? tf32r(s) : s;
    }
}

// ---------------- CoPE + softmax per row ----------------
__global__ void cope_softmax_kernel() {
    int i = blockIdx.x, h = blockIdx.y, b = blockIdx.z;
    int tid = threadIdx.x;
    size_t rowbase = (((size_t)(b * HH + h)) * NN + i) * NN;

    __shared__ float lrow[MAXP];
    __shared__ float wsum[8], woff[8];
    __shared__ float s_total, s_m, s_sum;

    if (tid < MAXP)
        lrow[tid] = g_logits[(((size_t)(b * HH + h)) * NN + i) * MAXP + tid];

    int j0 = tid * 4;
    float v[4], g[4];
#pragma unroll
    for (int c = 0; c < 4; c++) {
        int j = j0 + c;
        if (j <= i) { v[c] = g_sim2[rowbase + j]; g[c] = sigmoidf_(v[c]); }
        else        { v[c] = NEGV;               g[c] = 0.f; }
    }
    float lp[4];
    lp[0] = 0.f; lp[1] = g[0]; lp[2] = lp[1] + g[1]; lp[3] = lp[2] + g[2];
    float tsum = lp[3] + g[3];

    unsigned lane = tid & 31, wid = tid >> 5;
    float incl = tsum;
#pragma unroll
    for (int o = 1; o < 32; o <<= 1) {
        float t = __shfl_up_sync(0xffffffffu, incl, o);
        if (lane >= o) incl += t;
    }
    if (lane == 31) wsum[wid] = incl;
    __syncthreads();
    if (tid == 0) {
        float run = 0.f;
        for (int w = 0; w < 8; w++) { woff[w] = run; run += wsum[w]; }
        s_total = run;
    }
    __syncthreads();
    float basex = (incl - tsum) + woff[wid];
    float total = s_total;

    float nv[4];
#pragma unroll
    for (int c = 0; c < 4; c++) {
        int j = j0 + c;
        if (j <= i) {
            float pos = total - (basex + lp[c]);
            pos = fminf(fmaxf(pos, 0.f), 15.0f);
            float pf = floorf(pos);
            float w  = pos - pf;
            int fi = (int)pf;
            int ci = (int)ceilf(pos);
            nv[c] = v[c] + lrow[ci] * w + lrow[fi] * (1.0f - w);
        } else nv[c] = NEGV;
    }
    float m = fmaxf(fmaxf(nv[0], nv[1]), fmaxf(nv[2], nv[3]));
#pragma unroll
    for (int o = 16; o > 0; o >>= 1) m = fmaxf(m, __shfl_xor_sync(0xffffffffu, m, o));
    if (lane == 0) wsum[wid] = m;
    __syncthreads();
    if (tid == 0) {
        float mm = wsum[0];
        for (int w = 1; w < 8; w++) mm = fmaxf(mm, wsum[w]);
        s_m = mm;
    }
    __syncthreads();
    m = s_m;
    float e[4]; float ls = 0.f;
#pragma unroll
    for (int c = 0; c < 4; c++) { e[c] = expf(nv[c] - m); ls += e[c]; }
#pragma unroll
    for (int o = 16; o > 0; o >>= 1) ls += __shfl_xor_sync(0xffffffffu, ls, o);
    if (lane == 0) woff[wid] = ls;
    __syncthreads();
    if (tid == 0) {
        float t = 0.f;
        for (int w = 0; w < 8; w++) t += woff[w];
        s_sum = t;
    }
    __syncthreads();
    float invs = 1.0f / s_sum;
#pragma unroll
    for (int c = 0; c < 4; c++) {
        int j = j0 + c;
        if (j <= i) g_sim[rowbase + j] = e[c] * invs;
    }
}

// ---------------- head gate ----------------
__global__ void hgate_kernel(const float* __restrict__ x, const float* __restrict__ wh,
                             const float* __restrict__ bh) {
    int token = blockIdx.x;
    __shared__ __align__(16) float sx[DIMM];
    int tid = threadIdx.x;
    *(float4*)&sx[tid * 4] = *(const float4*)&x[(size_t)token * DIMM + tid * 4];
    __syncthreads();
    int h = tid >> 5, lane = tid & 31;
    float s = 0.f;
    for (int e = lane; e < DIMM; e += 32) s = fmaf(sx[e], wh[e * HH + h], s);
#pragma unroll
    for (int o = 16; o > 0; o >>= 1) s += __shfl_xor_sync(0xffffffffu, s, o);
    if (lane == 0) g_hg[token * HH + h] = sigmoidf_(s + bh[h]);
}

// ---------------- apply gates, merge heads (tf32-rounded output) ----------------
__global__ void gate_mul_kernel() {
    int idx = blockIdx.x * 256 + threadIdx.x;
    int token = idx >> 11;
    int c = idx & 2047;
    int h = c >> 7, d = c & 127;
    int b = token >> 10, n = token & 1023;
    float o = g_outh[(((size_t)(b * HH + h)) * NN + n) * DHH + d];
    g_gated[idx] = tf32r(o * g_hg[token * HH + h] * g_vg[idx]);
}

// ---------------- launch ----------------
extern "C" void kernel_launch(void* const* d_in, const int* in_sizes, int n_in,
                              void* d_out, int out_size) {
    const float* x    = (const float*)d_in[0];
    const float* rf   = (const float*)d_in[1];
    const float* wq   = (const float*)d_in[2];
    const float* wk   = (const float*)d_in[3];
    const float* wv   = (const float*)d_in[4];
    const float* cope = (const float*)d_in[5];
    const float* thp  = (const float*)d_in[6];
    const float* tho  = (const float*)d_in[7];
    const float* wvg  = (const float*)d_in[8];
    const float* bvg  = (const float*)d_in[9];
    const float* whg  = (const float*)d_in[10];
    const float* bhg  = (const float*)d_in[11];
    const float* wout = (const float*)d_in[12];
    float* out = (float*)d_out;

    cudaFuncSetAttribute(gemm_tc, cudaFuncAttributeMaxDynamicSharedMemorySize, SMEM_BYTES);

    void *pq, *pk, *pv, *pvt, *psim, *psim2, *pouth, *pvg, *pgated, *pxr;
    void *pwqT, *pwkT, *pwvT, *pwvgT, *pwoutT;
    cudaGetSymbolAddress(&pq, g_q);
    cudaGetSymbolAddress(&pk, g_k);
    cudaGetSymbolAddress(&pv, g_v);
    cudaGetSymbolAddress(&pvt, g_vt);
    cudaGetSymbolAddress(&psim, g_sim);
    cudaGetSymbolAddress(&psim2, g_sim2);
    cudaGetSymbolAddress(&pouth, g_outh);
    cudaGetSymbolAddress(&pvg, g_vg);
    cudaGetSymbolAddress(&pgated, g_gated);
    cudaGetSymbolAddress(&pxr, g_xr);
    cudaGetSymbolAddress(&pwqT, g_wqT);
    cudaGetSymbolAddress(&pwkT, g_wkT);
    cudaGetSymbolAddress(&pwvT, g_wvT);
    cudaGetSymbolAddress(&pwvgT, g_wvgT);
    cudaGetSymbolAddress(&pwoutT, g_woutT);

    dim3 gBig(16, 16, 1);
    dim3 tBlk(32, 8);
    dim3 tGrd(64, 64, 1);

    rope_cs_kernel<<<NN * DHH / 256, 256>>>(rf);

    // pre-pass: transpose+round weights, round x
    transpose_round<<<tGrd, tBlk>>>(wq,   (float*)pwqT,   DIMM, HD, 0, 0);
    transpose_round<<<tGrd, tBlk>>>(wk,   (float*)pwkT,   DIMM, HD, 0, 0);
    transpose_round<<<tGrd, tBlk>>>(wv,   (float*)pwvT,   DIMM, HD, 0, 0);
    transpose_round<<<tGrd, tBlk>>>(wvg,  (float*)pwvgT,  DIMM, HD, 0, 0);
    transpose_round<<<tGrd, tBlk>>>(wout, (float*)pwoutT, HD, DIMM, 0, 0);
    round_copy<<<TT * DIMM / 1024, 256>>>(x, (float*)pxr);

    // QKV projections
    gemm_tc<<<gBig, 256, SMEM_BYTES>>>((float*)pxr, DIMM, 0, 0, (float*)pwqT, DIMM, 0, 0,
                                       (float*)pq, HD, 0, 0, DIMM, 0, nullptr, 1.f);
    gemm_tc<<<gBig, 256, SMEM_BYTES>>>((float*)pxr, DIMM, 0, 0, (float*)pwkT, DIMM, 0, 0,
                                       (float*)pk, HD, 0, 0, DIMM, 0, nullptr, 1.f);
    gemm_tc<<<gBig, 256, SMEM_BYTES>>>((float*)pxr, DIMM, 0, 0, (float*)pwvT, DIMM, 0, 0,
                                       (float*)pv, HD, 0, 0, DIMM, 0, nullptr, 1.f);

    norm_rot2_kernel<<<8192, 256>>>(cope);

    // V transpose per batch: g_vt[b][c][n] = tf32(g_v[b*NN + n][c])
    transpose_round<<<dim3(64, 32, BB), tBlk>>>((float*)pv, (float*)pvt, NN, HD,
                                                (long long)NN * HD, (long long)HD * NN);

    // sim = 10 * Q @ K^T (causal tiles only)
    gemm_tc<<<dim3(8, 8, BB * HH), 256, SMEM_BYTES>>>(
        (float*)pq, HD, (long long)NN * HD, DHH,
        (float*)pk, HD, (long long)NN * HD, DHH,
        (float*)psim, NN, 16LL * NN * NN, (long long)NN * NN,
        DHH, 2, nullptr, 10.0f);

    mix_heads_kernel<<<dim3(4, NN, BB), 256>>>(thp, 0);   // g_sim -> g_sim2
    cope_softmax_kernel<<<dim3(NN, HH, BB), 256>>>();     // g_sim2 -> attn in g_sim
    mix_heads_kernel<<<dim3(4, NN, BB), 256>>>(tho, 1);   // g_sim -> g_sim2 (tf32)

    // out = attn2 @ V  (B = Vt [d][j]; triangular K; upper band of g_sim2 is zero)
    gemm_tc<<<dim3(1, 8, BB * HH), 256, SMEM_BYTES>>>(
        (float*)psim2, NN, 16LL * NN * NN, (long long)NN * NN,
        (float*)pvt, NN, (long long)HD * NN, (long long)DHH * NN,
        (float*)pouth, DHH, 16LL * NN * DHH, (long long)NN * DHH,
        NN, 4, nullptr, 1.f);

    hgate_kernel<<<TT, 512>>>(x, whg, bhg);
    gemm_tc<<<gBig, 256, SMEM_BYTES>>>((float*)pxr, DIMM, 0, 0, (float*)pwvgT, DIMM, 0, 0,
                                       (float*)pvg, HD, 0, 0, DIMM, 8, bvg, 1.f);
    gate_mul_kernel<<<(TT * HD) / 256, 256>>>();

    gemm_tc<<<gBig, 256, SMEM_BYTES>>>((float*)pgated, HD, 0, 0, (float*)pwoutT, HD, 0, 0,
                                       out, DIMM, 0, 0, HD, 0, nullptr, 1.f);
}